// round 8
// baseline (speedup 1.0000x reference)
#include <cuda_runtime.h>

// ChannelPruner: out[b,o,h,w] = sum_c W[o,c] * x[b,c,h,w]
//  - Kernel 1: warp-per-row ballot+popc compaction (~2us measured).
//  - Kernel 2: flat streaming sparse-dot with ILP=4: each thread computes four
//    output float4 at p4 + {0,196,392,588} within one (b,o) plane.
// Measured: ILP=1 -> 29.5us @55% DRAM; ILP=2 -> 26.75us @60% DRAM.
// This continues the MLP axis (B300: lat_DRAM/MLP + C model).

#define N_CH   256
#define HW4    784               // 56*56/4 float4 per channel-plane
#define QTR4   196
#define BATCH  32
#define TOTAL4 (BATCH * N_CH * HW4)    // 6,422,528 float4
#define NTHREAD (TOTAL4 / 4)           // 1,605,632 threads, 4 outputs each

__device__ int   g_nnz[N_CH];
__device__ int   g_col[N_CH * N_CH];
__device__ float g_val[N_CH * N_CH];

// --- Kernel 1: warp-per-row compaction (32 blocks x 8 warps = 256 warps) ---
__global__ void __launch_bounds__(256)
compact_rows_kernel(const float* __restrict__ w) {
    const int warp = threadIdx.x >> 5;
    const int lane = threadIdx.x & 31;
    const int o    = blockIdx.x * 8 + warp;      // 0..255

    const float* row = w + o * N_CH;
    int*   cols = g_col + o * N_CH;
    float* vals = g_val + o * N_CH;

    int off = 0;
    #pragma unroll
    for (int ch = 0; ch < N_CH / 32; ++ch) {
        float v = row[ch * 32 + lane];
        unsigned m = __ballot_sync(0xffffffffu, v != 0.0f);
        int pre = __popc(m & ((1u << lane) - 1u));
        if (v != 0.0f) {
            cols[off + pre] = ch * 32 + lane;
            vals[off + pre] = v;
        }
        off += __popc(m);
    }
    if (lane == 0) g_nnz[o] = off;
}

// --- Kernel 2: streaming sparse-dot, 4 float4 per thread (same plane) ---
__global__ void __launch_bounds__(256)
prune_stream_kernel(const float* __restrict__ x, float* __restrict__ out) {
    const int idx = blockIdx.x * 256 + threadIdx.x;   // 0..NTHREAD-1

    const int p4 = idx % QTR4;        // 0..195 (umulhi magic division)
    const int bo = idx / QTR4;        // b*256 + o
    const int o  = bo & (N_CH - 1);
    const int b  = bo >> 8;

    const int n = g_nnz[o];

    const float4* xb   = (const float4*)x + b * (N_CH * HW4) + p4;
    const int*    cols = g_col + o * N_CH;
    const float*  vals = g_val + o * N_CH;

    float4 acc0 = make_float4(0.f, 0.f, 0.f, 0.f);
    float4 acc1 = acc0, acc2 = acc0, acc3 = acc0;

    for (int j = 0; j < n; ++j) {
        float v = vals[j];
        const float4* xc = xb + cols[j] * HW4;
        float4 xv0 = xc[0];           // 4 independent loads -> MLP 4
        float4 xv1 = xc[QTR4];
        float4 xv2 = xc[2 * QTR4];
        float4 xv3 = xc[3 * QTR4];
        acc0.x = fmaf(v, xv0.x, acc0.x);
        acc0.y = fmaf(v, xv0.y, acc0.y);
        acc0.z = fmaf(v, xv0.z, acc0.z);
        acc0.w = fmaf(v, xv0.w, acc0.w);
        acc1.x = fmaf(v, xv1.x, acc1.x);
        acc1.y = fmaf(v, xv1.y, acc1.y);
        acc1.z = fmaf(v, xv1.z, acc1.z);
        acc1.w = fmaf(v, xv1.w, acc1.w);
        acc2.x = fmaf(v, xv2.x, acc2.x);
        acc2.y = fmaf(v, xv2.y, acc2.y);
        acc2.z = fmaf(v, xv2.z, acc2.z);
        acc2.w = fmaf(v, xv2.w, acc2.w);
        acc3.x = fmaf(v, xv3.x, acc3.x);
        acc3.y = fmaf(v, xv3.y, acc3.y);
        acc3.z = fmaf(v, xv3.z, acc3.z);
        acc3.w = fmaf(v, xv3.w, acc3.w);
    }

    float4* ob = (float4*)out + bo * HW4 + p4;
    ob[0]        = acc0;
    ob[QTR4]     = acc1;
    ob[2 * QTR4] = acc2;
    ob[3 * QTR4] = acc3;
}

extern "C" void kernel_launch(void* const* d_in, const int* in_sizes, int n_in,
                              void* d_out, int out_size) {
    const float* x = (const float*)d_in[0];   // (32,256,56,56) fp32
    const float* w = (const float*)d_in[1];   // (256,256,1,1)  fp32
    float* out = (float*)d_out;

    compact_rows_kernel<<<32, 256>>>(w);

    prune_stream_kernel<<<NTHREAD / 256, 256>>>(x, out);   // 6272 blocks
}

// round 11
// speedup vs baseline: 1.0036x; 1.0036x over previous
#include <cuda_runtime.h>

// ChannelPruner: out[b,o,h,w] = sum_c W[o,c] * x[b,c,h,w]
//  - Kernel 1: warp-per-row compaction, loads FRONT-BATCHED (MLP=8) so the
//    row scan pays one DRAM latency instead of eight (~2.7us -> ~0.6us).
//  - Kernel 2: flat streaming sparse-dot, ILP=2 (best measured: 26.75us,
//    DRAM 60%; ILP=4 measured equal -> keep the lower-register variant).

#define N_CH   256
#define HW4    784               // 56*56/4 float4 per channel-plane
#define HALF4  392
#define BATCH  32
#define TOTAL4 (BATCH * N_CH * HW4)    // 6,422,528 float4
#define NTHREAD (TOTAL4 / 2)           // one thread per 2 outputs

__device__ int   g_nnz[N_CH];
__device__ int   g_col[N_CH * N_CH];
__device__ float g_val[N_CH * N_CH];

// --- Kernel 1: warp-per-row compaction, front-batched loads ---
__global__ void __launch_bounds__(256)
compact_rows_kernel(const float* __restrict__ w) {
    const int warp = threadIdx.x >> 5;
    const int lane = threadIdx.x & 31;
    const int o    = blockIdx.x * 8 + warp;      // 0..255

    const float* row = w + o * N_CH;

    // issue all 8 loads before any use: one exposed DRAM latency, not eight
    float v[8];
    #pragma unroll
    for (int ch = 0; ch < 8; ++ch) v[ch] = row[ch * 32 + lane];

    int*   cols = g_col + o * N_CH;
    float* vals = g_val + o * N_CH;

    int off = 0;
    #pragma unroll
    for (int ch = 0; ch < 8; ++ch) {
        unsigned m = __ballot_sync(0xffffffffu, v[ch] != 0.0f);
        int pre = __popc(m & ((1u << lane) - 1u));
        if (v[ch] != 0.0f) {
            cols[off + pre] = ch * 32 + lane;
            vals[off + pre] = v[ch];
        }
        off += __popc(m);
    }
    if (lane == 0) g_nnz[o] = off;
}

// --- Kernel 2: streaming sparse-dot, 2 float4 per thread (same plane) ---
__global__ void __launch_bounds__(256)
prune_stream_kernel(const float* __restrict__ x, float* __restrict__ out) {
    const int idx = blockIdx.x * 256 + threadIdx.x;   // 0..NTHREAD-1

    const int p4 = idx % HALF4;       // 0..391 (umulhi magic division)
    const int bo = idx / HALF4;       // b*256 + o
    const int o  = bo & (N_CH - 1);
    const int b  = bo >> 8;

    const int n = g_nnz[o];

    const float4* xb   = (const float4*)x + b * (N_CH * HW4) + p4;
    const int*    cols = g_col + o * N_CH;
    const float*  vals = g_val + o * N_CH;

    float4 acc0 = make_float4(0.f, 0.f, 0.f, 0.f);
    float4 acc1 = acc0;

    for (int j = 0; j < n; ++j) {
        float v = vals[j];
        const float4* xc = xb + cols[j] * HW4;
        float4 xv0 = xc[0];           // independent loads -> MLP 2
        float4 xv1 = xc[HALF4];
        acc0.x = fmaf(v, xv0.x, acc0.x);
        acc0.y = fmaf(v, xv0.y, acc0.y);
        acc0.z = fmaf(v, xv0.z, acc0.z);
        acc0.w = fmaf(v, xv0.w, acc0.w);
        acc1.x = fmaf(v, xv1.x, acc1.x);
        acc1.y = fmaf(v, xv1.y, acc1.y);
        acc1.z = fmaf(v, xv1.z, acc1.z);
        acc1.w = fmaf(v, xv1.w, acc1.w);
    }

    float4* ob = (float4*)out + bo * HW4 + p4;
    ob[0]     = acc0;
    ob[HALF4] = acc1;
}

extern "C" void kernel_launch(void* const* d_in, const int* in_sizes, int n_in,
                              void* d_out, int out_size) {
    const float* x = (const float*)d_in[0];   // (32,256,56,56) fp32
    const float* w = (const float*)d_in[1];   // (256,256,1,1)  fp32
    float* out = (float*)d_out;

    compact_rows_kernel<<<32, 256>>>(w);

    prune_stream_kernel<<<NTHREAD / 256, 256>>>(x, out);   // 12544 blocks
}

// round 12
// speedup vs baseline: 1.0654x; 1.0616x over previous
#include <cuda_runtime.h>

// ChannelPruner: out[b,o,h,w] = sum_c W[o,c] * x[b,c,h,w]
// SINGLE fused kernel. Flat ILP=2 mapping (best measured stream: 26.75us,
// DRAM 60%). A 256-thread block spans at most 2 consecutive bo planes
// (256 < 392), so warps 0/1 each compact one W row (ballot+popc, loads
// front-batched) into double-buffered smem; one barrier; then stream.
// This removes the second graph launch (~8.5us non-stream time measured
// in the two-kernel variant, dominated by launch gap, not compaction work).

#define N_CH   256
#define HW4    784               // 56*56/4 float4 per channel-plane
#define HALF4  392
#define BATCH  32
#define TOTAL4 (BATCH * N_CH * HW4)    // 6,422,528 float4
#define NTHREAD (TOTAL4 / 2)           // one thread per 2 outputs

__global__ void __launch_bounds__(256)
fused_prune_kernel(const float* __restrict__ x,
                   const float* __restrict__ w,
                   float* __restrict__ out) {
    __shared__ int   s_col[2][N_CH];
    __shared__ float s_val[2][N_CH];
    __shared__ int   s_nnz[2];

    const int base = blockIdx.x * 256;
    const int idx  = base + threadIdx.x;            // 0..NTHREAD-1

    const int bo_first = base / HALF4;              // first plane this block touches
    const int warp = threadIdx.x >> 5;
    const int lane = threadIdx.x & 31;

    // --- warps 0 and 1: compact the (<=2) W rows this block needs ---
    if (warp < 2) {
        const int bo_w = (warp == 0) ? bo_first : (base + 255) / HALF4;
        const int o_w  = bo_w & (N_CH - 1);
        const float* row = w + o_w * N_CH;

        float v[8];
        #pragma unroll
        for (int ch = 0; ch < 8; ++ch) v[ch] = row[ch * 32 + lane];  // MLP=8

        int off = 0;
        #pragma unroll
        for (int ch = 0; ch < 8; ++ch) {
            unsigned m = __ballot_sync(0xffffffffu, v[ch] != 0.0f);
            int pre = __popc(m & ((1u << lane) - 1u));
            if (v[ch] != 0.0f) {
                s_col[warp][off + pre] = ch * 32 + lane;
                s_val[warp][off + pre] = v[ch];
            }
            off += __popc(m);
        }
        if (lane == 0) s_nnz[warp] = off;
    }
    __syncthreads();

    // --- stream: 2 float4 per thread within one (b,o) plane ---
    const int p4 = idx % HALF4;       // umulhi magic division
    const int bo = idx / HALF4;
    const int b  = bo >> 8;
    const int slot = (bo != bo_first);   // 0 or 1

    const int n = s_nnz[slot];
    const int*   cols = s_col[slot];
    const float* vals = s_val[slot];

    const float4* xb = (const float4*)x + b * (N_CH * HW4) + p4;

    float4 acc0 = make_float4(0.f, 0.f, 0.f, 0.f);
    float4 acc1 = acc0;

    for (int j = 0; j < n; ++j) {
        float v = vals[j];
        const float4* xc = xb + cols[j] * HW4;
        float4 xv0 = xc[0];           // independent loads -> MLP 2
        float4 xv1 = xc[HALF4];
        acc0.x = fmaf(v, xv0.x, acc0.x);
        acc0.y = fmaf(v, xv0.y, acc0.y);
        acc0.z = fmaf(v, xv0.z, acc0.z);
        acc0.w = fmaf(v, xv0.w, acc0.w);
        acc1.x = fmaf(v, xv1.x, acc1.x);
        acc1.y = fmaf(v, xv1.y, acc1.y);
        acc1.z = fmaf(v, xv1.z, acc1.z);
        acc1.w = fmaf(v, xv1.w, acc1.w);
    }

    float4* ob = (float4*)out + bo * HW4 + p4;
    ob[0]     = acc0;
    ob[HALF4] = acc1;
}

extern "C" void kernel_launch(void* const* d_in, const int* in_sizes, int n_in,
                              void* d_out, int out_size) {
    const float* x = (const float*)d_in[0];   // (32,256,56,56) fp32
    const float* w = (const float*)d_in[1];   // (256,256,1,1)  fp32
    float* out = (float*)d_out;

    fused_prune_kernel<<<NTHREAD / 256, 256>>>(x, w, out);   // 12544 blocks
}